// round 8
// baseline (speedup 1.0000x reference)
#include <cuda_runtime.h>
#include <cstdint>
#include <math.h>

typedef unsigned long long ull;

#define Bv 32
#define Lv 1024
#define Hv 512
#define NGROUP 8
#define CPG 16
#define ROWP 516   // padded row stride (floats) in smem: conflict-free LDS.128

// ---------------- device scratch (no cudaMalloc allowed) ----------------
__device__ float g_pre[(size_t)Lv * Bv * 1536];   // [t][b][0..1023]=x_ru+b_ru, [1024..1535]=x_c+b_c
__device__ float g_h [Bv * Hv];
__device__ float g_rh[Bv * Hv];
__device__ float g_z [Bv * Hv];
// one flag per CTA, each on its OWN 128-byte line (32 uints apart)
__device__ unsigned int g_flag[NGROUP * CPG * 32];   // zero-init; monotonic across replays

// ---------------- f32x2 helpers ----------------
__device__ __forceinline__ ull splat2(float x) {
    ull r; asm("mov.b64 %0, {%1, %1};" : "=l"(r) : "f"(x)); return r;
}
__device__ __forceinline__ float2 unpack2(ull v) {
    float2 f; asm("mov.b64 {%0, %1}, %2;" : "=f"(f.x), "=f"(f.y) : "l"(v)); return f;
}
__device__ __forceinline__ void ffma2(ull& d, ull a, ull b) {
    asm("fma.rn.f32x2 %0, %1, %2, %0;" : "+l"(d) : "l"(a), "l"(b));
}
__device__ __forceinline__ float fast_sigmoid(float x) {
    x = fminf(fmaxf(x, -30.0f), 30.0f);
    return 1.0f / (1.0f + __expf(-x));
}
__device__ __forceinline__ float fast_tanh(float x) {
    x = fminf(fmaxf(x, -15.0f), 15.0f);
    float e = __expf(2.0f * x);
    return (e - 1.0f) / (e + 1.0f);
}

__device__ __forceinline__ void dot16(const ulonglong2* __restrict__ wp,
                                      const ulonglong2* __restrict__ hp,
                                      int k, ull* acc) {
    ulonglong2 w0 = wp[4*k+0], w1 = wp[4*k+1], w2 = wp[4*k+2], w3 = wp[4*k+3];
    ulonglong2 h0 = hp[4*k+0], h1 = hp[4*k+1], h2 = hp[4*k+2], h3 = hp[4*k+3];
    ffma2(acc[0], w0.x, h0.x); ffma2(acc[1], w0.y, h0.y);
    ffma2(acc[2], w1.x, h1.x); ffma2(acc[3], w1.y, h1.y);
    ffma2(acc[4], w2.x, h2.x); ffma2(acc[5], w2.y, h2.y);
    ffma2(acc[6], w3.x, h3.x); ffma2(acc[7], w3.y, h3.y);
}
__device__ __forceinline__ float acc8_sum(const ull* acc) {
    float2 f0 = unpack2(acc[0]), f1 = unpack2(acc[1]), f2 = unpack2(acc[2]), f3 = unpack2(acc[3]);
    float2 f4 = unpack2(acc[4]), f5 = unpack2(acc[5]), f6 = unpack2(acc[6]), f7 = unpack2(acc[7]);
    float s0 = (f0.x + f0.y) + (f1.x + f1.y);
    float s1 = (f2.x + f2.y) + (f3.x + f3.y);
    float s2 = (f4.x + f4.y) + (f5.x + f5.y);
    float s3 = (f6.x + f6.y) + (f7.x + f7.y);
    return (s0 + s1) + (s2 + s3);
}

// ---------------- kernel 1: projection GEMM (fp32, f32x2) ----------------
__global__ void __launch_bounds__(256) gemm_pre(const float* __restrict__ x,
                                                const float* __restrict__ W_ru,
                                                const float* __restrict__ W_c,
                                                const float* __restrict__ b_ru,
                                                const float* __restrict__ b_c) {
    __shared__ float As[2][64 * 36];
    __shared__ float Bs[2][32 * 64];
    const int tid = threadIdx.x;
    const int n0 = blockIdx.x * 64;
    const int m0 = blockIdx.y * 64;

    const float* Wsrc = (n0 < 1024) ? (W_ru + (size_t)n0 * 1024 + 512)
                                    : (W_c + (size_t)(n0 - 1024) * 1024 + 512);

    const int arow = tid >> 3, ac = (tid & 7) * 4;
    const float* Ap0 = x + (size_t)(m0 + arow) * 512 + ac;
    const int bn = tid & 63, bk = (tid >> 6) * 4;
    const float* Bp0 = Wsrc + (size_t)bn * 1024 + bk;

    const int tx = tid & 15, ty = tid >> 4;

    ull acc[4][2];
#pragma unroll
    for (int i = 0; i < 4; i++) { acc[i][0] = 0ull; acc[i][1] = 0ull; }

    float4 ra0 = *(const float4*)(Ap0);
    float4 ra1 = *(const float4*)(Ap0 + 32 * 512);
    float4 rb0 = *(const float4*)(Bp0);
    float4 rb1 = *(const float4*)(Bp0 + 16);

    *(float4*)&As[0][arow * 36 + ac] = ra0;
    *(float4*)&As[0][(arow + 32) * 36 + ac] = ra1;
    Bs[0][(bk + 0) * 64 + bn] = rb0.x; Bs[0][(bk + 1) * 64 + bn] = rb0.y;
    Bs[0][(bk + 2) * 64 + bn] = rb0.z; Bs[0][(bk + 3) * 64 + bn] = rb0.w;
    Bs[0][(bk + 16) * 64 + bn] = rb1.x; Bs[0][(bk + 17) * 64 + bn] = rb1.y;
    Bs[0][(bk + 18) * 64 + bn] = rb1.z; Bs[0][(bk + 19) * 64 + bn] = rb1.w;
    __syncthreads();

    for (int kt = 0; kt < 16; kt++) {
        const int cur = kt & 1;
        if (kt < 15) {
            const float* ap = Ap0 + (kt + 1) * 32;
            ra0 = *(const float4*)(ap);
            ra1 = *(const float4*)(ap + 32 * 512);
            const float* bp = Bp0 + (kt + 1) * 32;
            rb0 = *(const float4*)(bp);
            rb1 = *(const float4*)(bp + 16);
        }
        const float* Arow = &As[cur][ty * 4 * 36];
        const float* Bbase = &Bs[cur][0];
#pragma unroll
        for (int kk = 0; kk < 32; kk++) {
            float av0 = Arow[kk], av1 = Arow[36 + kk], av2 = Arow[72 + kk], av3 = Arow[108 + kk];
            const ull* Bq = (const ull*)(Bbase + kk * 64);
            ull b0 = Bq[tx * 2], b1 = Bq[tx * 2 + 1];
            ull s0 = splat2(av0), s1 = splat2(av1), s2 = splat2(av2), s3 = splat2(av3);
            ffma2(acc[0][0], s0, b0); ffma2(acc[0][1], s0, b1);
            ffma2(acc[1][0], s1, b0); ffma2(acc[1][1], s1, b1);
            ffma2(acc[2][0], s2, b0); ffma2(acc[2][1], s2, b1);
            ffma2(acc[3][0], s3, b0); ffma2(acc[3][1], s3, b1);
        }
        if (kt < 15) {
            const int nb = (kt + 1) & 1;
            *(float4*)&As[nb][arow * 36 + ac] = ra0;
            *(float4*)&As[nb][(arow + 32) * 36 + ac] = ra1;
            Bs[nb][(bk + 0) * 64 + bn] = rb0.x; Bs[nb][(bk + 1) * 64 + bn] = rb0.y;
            Bs[nb][(bk + 2) * 64 + bn] = rb0.z; Bs[nb][(bk + 3) * 64 + bn] = rb0.w;
            Bs[nb][(bk + 16) * 64 + bn] = rb1.x; Bs[nb][(bk + 17) * 64 + bn] = rb1.y;
            Bs[nb][(bk + 18) * 64 + bn] = rb1.z; Bs[nb][(bk + 19) * 64 + bn] = rb1.w;
        }
        __syncthreads();
    }

    const float* bias = (n0 < 1024) ? (b_ru + n0) : (b_c + (n0 - 1024));
    const float4 bv = *(const float4*)&bias[tx * 4];
#pragma unroll
    for (int i = 0; i < 4; i++) {
        int m = m0 + ty * 4 + i;
        int bb = m >> 10, tt = m & 1023;
        float2 f0 = unpack2(acc[i][0]);
        float2 f1 = unpack2(acc[i][1]);
        float4 o = make_float4(f0.x + bv.x, f0.y + bv.y, f1.x + bv.z, f1.y + bv.w);
        *(float4*)&g_pre[((size_t)tt * 32 + bb) * 1536 + n0 + tx * 4] = o;
    }
}

// ---------------- group barrier: padded flags, release signal + acquire poll ----------------
__device__ __forceinline__ void bar_signal(int grp, int c, unsigned target) {
    asm volatile("st.release.gpu.u32 [%0], %1;"
                 :: "l"(g_flag + ((size_t)(grp * CPG + c) * 32)), "r"(target) : "memory");
}
__device__ __forceinline__ void bar_poll(int grp, unsigned target) {
    if (threadIdx.x < CPG) {
        const unsigned* fp = g_flag + ((size_t)(grp * CPG + threadIdx.x) * 32);
        unsigned v;
        do {
            asm volatile("ld.acquire.gpu.u32 %0, [%1];" : "=r"(v) : "l"(fp) : "memory");
        } while ((int)(v - target) < 0);
    }
    __syncthreads();
}

// ---------------- kernel 2: persistent recurrent scan (512 threads) ----------------
// 128 CTAs = 8 groups x 16 CTAs, ~210KB smem (1 CTA/SM, all co-resident).
__global__ void __launch_bounds__(512, 1) scan_kernel(const float* __restrict__ W_ru,
                                                      const float* __restrict__ W_c,
                                                      const float* __restrict__ init_h,
                                                      float* __restrict__ out,
                                                      int has_last) {
    extern __shared__ float sm[];
    float* sWg = sm;                      // 64 x ROWP
    float* sWc = sWg + 64 * ROWP;         // 32 x ROWP
    float* sh  = sWc + 32 * ROWP;         // 4 x ROWP
    float* srh = sh + 4 * ROWP;           // 4 x ROWP
    __shared__ unsigned sBase;

    const int tid = threadIdx.x;
    const int grp = blockIdx.x >> 4;
    const int c   = blockIdx.x & 15;

    // own-flag base (only this CTA writes flag c; all group flags equal at entry)
    if (tid == 0) sBase = g_flag[(size_t)(grp * CPG + c) * 32];

    {
        const int gbase = c * 64;
        for (int i = tid; i < 64 * 128; i += 512) {
            int r = i >> 7, q = (i & 127) * 4;
            float4 v = *(const float4*)(W_ru + (size_t)(gbase + r) * 1024 + q);
            *(float4*)(sWg + r * ROWP + q) = v;
        }
        const int nbase = c * 32;
        for (int i = tid; i < 32 * 128; i += 512) {
            int r = i >> 7, q = (i & 127) * 4;
            float4 v = *(const float4*)(W_c + (size_t)(nbase + r) * 1024 + q);
            *(float4*)(sWc + r * ROWP + q) = v;
        }
    }
    {
        int b = tid >> 7, q = (tid & 127) * 4;
        float4 v = *(const float4*)(init_h + (size_t)(grp * 4 + b) * 512 + q);
        *(float4*)(sh + b * ROWP + q) = v;
    }
    __syncthreads();
    const unsigned base = sBase;

    // phase-1: pair of threads per (gate row, batch), k-split x2
    const int pr = tid >> 1, h1 = tid & 1;
    const int gl = pr >> 2, bl = pr & 3;
    const int ggl = c * 64 + gl;          // global gate row 0..1023
    const int gb  = grp * 4 + bl;         // global batch
    const ulonglong2* wg_p = (const ulonglong2*)(sWg + gl * ROWP + h1 * 256);
    const ulonglong2* sh_p = (const ulonglong2*)(sh + bl * ROWP + h1 * 256);

    // phase-2: quad of threads per (cand row, batch), k-split x4
    const int q4 = tid & 3, d2 = tid >> 2;
    const int nl = d2 >> 2, bl2 = d2 & 3;
    const int n   = c * 32 + nl;
    const int gb2 = grp * 4 + bl2;
    const ulonglong2* wc_p = (const ulonglong2*)(sWc + nl * ROWP + q4 * 128);

    const bool is_r = (ggl < 512);
    float* rz_dst = is_r ? (g_rh + (size_t)gb * 512 + ggl)
                         : (g_z + (size_t)gb * 512 + (ggl - 512));

    float xg = __ldg(&g_pre[(size_t)gb * 1536 + ggl]);

    for (int t = 0; t < Lv; t++) {
        // ---- phase 1: gates ----
        float xc = __ldg(&g_pre[((size_t)t * 32 + gb2) * 1536 + 1024 + n]);  // prefetch
        ull a[8];
#pragma unroll
        for (int i = 0; i < 8; i++) a[i] = 0ull;
#pragma unroll
        for (int k = 0; k < 16; k++) dot16(wg_p, sh_p, k, a);
        float pre = acc8_sum(a);
        pre += __shfl_xor_sync(0xffffffffu, pre, 1);
        if (h1 == 0) {
            float gate = fast_sigmoid(pre + xg);
            float val = is_r ? (gate * sh[bl * ROWP + ggl]) : gate;
            __stcg(rz_dst, val);
        }

        __syncthreads();
        if (tid == 0) bar_signal(grp, c, base + 2u * t + 1u);
        bar_poll(grp, base + 2u * t + 1u);

        // ---- stage rh (2048 floats, one float4 per thread) ----
        {
            int b = tid >> 7, q = (tid & 127) * 4;
            float4 v = __ldcg((const float4*)(g_rh + (size_t)(grp * 4 + b) * 512 + q));
            *(float4*)(srh + b * ROWP + q) = v;
        }
        float zv = __ldcg(&g_z[(size_t)gb2 * 512 + n]);
        __syncthreads();

        // ---- phase 2: candidate + blend ----
        const ulonglong2* srh_p = (const ulonglong2*)(srh + bl2 * ROWP + q4 * 128);
        ull ca[8];
#pragma unroll
        for (int i = 0; i < 8; i++) ca[i] = 0ull;
#pragma unroll
        for (int k = 0; k < 8; k++) dot16(wc_p, srh_p, k, ca);
        float tot = acc8_sum(ca);
        tot += __shfl_xor_sync(0xffffffffu, tot, 1);
        tot += __shfl_xor_sync(0xffffffffu, tot, 2);

        if (t < Lv - 1) xg = __ldg(&g_pre[((size_t)(t + 1) * 32 + gb) * 1536 + ggl]);

        float hnew = 0.0f;
        if (q4 == 0) {
            float cand = fast_tanh(tot + xc);
            float hold = sh[bl2 * ROWP + n];
            hnew = hold + zv * (cand - hold);
            __stcg(&g_h[(size_t)gb2 * 512 + n], hnew);
        }

        __syncthreads();
        if (tid == 0) bar_signal(grp, c, base + 2u * t + 2u);

        // out-store off the critical path (no one reads it; poll overlaps the DRAM write)
        if (q4 == 0) {
            out[(size_t)gb2 * ((size_t)Lv * 512) + (size_t)t * 512 + n] = hnew;
            if (has_last && t == Lv - 1)
                out[(size_t)Bv * Lv * 512 + (size_t)gb2 * 512 + n] = hnew;
        }

        bar_poll(grp, base + 2u * t + 2u);

        // ---- restage h for next step ----
        if (t < Lv - 1) {
            int b = tid >> 7, q = (tid & 127) * 4;
            float4 v = __ldcg((const float4*)(g_h + (size_t)(grp * 4 + b) * 512 + q));
            *(float4*)(sh + b * ROWP + q) = v;
            __syncthreads();
        }
    }
}

// ---------------- launch ----------------
extern "C" void kernel_launch(void* const* d_in, const int* in_sizes, int n_in,
                              void* d_out, int out_size) {
    const float* x      = (const float*)d_in[0];
    const float* init_h = (const float*)d_in[1];
    const float* W_ru   = (const float*)d_in[2];
    const float* b_ru   = (const float*)d_in[3];
    const float* W_c    = (const float*)d_in[4];
    const float* b_c    = (const float*)d_in[5];
    float* out = (float*)d_out;

    const int scan_smem = (64 * ROWP + 32 * ROWP + 8 * ROWP) * 4;  // 214,656 B
    cudaFuncSetAttribute(scan_kernel, cudaFuncAttributeMaxDynamicSharedMemorySize, scan_smem);

    int has_last = (out_size >= Bv * Lv * Hv + Bv * Hv) ? 1 : 0;

    gemm_pre<<<dim3(24, 512), 256>>>(x, W_ru, W_c, b_ru, b_c);
    scan_kernel<<<NGROUP * CPG, 512, scan_smem>>>(W_ru, W_c, init_h, out, has_last);
}

// round 9
// speedup vs baseline: 1.9077x; 1.9077x over previous
#include <cuda_runtime.h>
#include <cstdint>
#include <math.h>

typedef unsigned long long ull;

#define Bv 32
#define Lv 1024
#define Hv 512
#define NGROUP 8
#define CPG 16
#define ROWP 516   // padded row stride (floats) in smem

// ---------------- device scratch (no cudaMalloc allowed) ----------------
__device__ float g_pre[(size_t)Lv * Bv * 1536];   // [t][b][0..1023]=x_ru+b_ru, [1024..1535]=x_c+b_c
__device__ float g_h [Bv * Hv];
__device__ float g_rh[Bv * Hv];
__device__ float g_z [Bv * Hv];
// one flag per CTA, each on its OWN 128-byte line
__device__ unsigned int g_flag[NGROUP * CPG * 32];   // zero-init; monotonic across replays

// ---------------- f32x2 helpers ----------------
__device__ __forceinline__ ull splat2(float x) {
    ull r; asm("mov.b64 %0, {%1, %1};" : "=l"(r) : "f"(x)); return r;
}
__device__ __forceinline__ float2 unpack2(ull v) {
    float2 f; asm("mov.b64 {%0, %1}, %2;" : "=f"(f.x), "=f"(f.y) : "l"(v)); return f;
}
__device__ __forceinline__ void ffma2(ull& d, ull a, ull b) {
    asm("fma.rn.f32x2 %0, %1, %2, %0;" : "+l"(d) : "l"(a), "l"(b));
}
__device__ __forceinline__ float fast_sigmoid(float x) {
    x = fminf(fmaxf(x, -30.0f), 30.0f);
    return 1.0f / (1.0f + __expf(-x));
}
__device__ __forceinline__ float fast_tanh(float x) {
    x = fminf(fmaxf(x, -15.0f), 15.0f);
    float e = __expf(2.0f * x);
    return (e - 1.0f) / (e + 1.0f);
}

// 16 floats of w x 16 floats of h (4 ull2 each) -> 8 FFMA2 into 8 accumulators
__device__ __forceinline__ void dot16(const ulonglong2* __restrict__ wp,
                                      const ulonglong2* __restrict__ hp, ull* acc) {
    ulonglong2 w0 = wp[0], w1 = wp[1], w2 = wp[2], w3 = wp[3];
    ulonglong2 h0 = hp[0], h1 = hp[1], h2 = hp[2], h3 = hp[3];
    ffma2(acc[0], w0.x, h0.x); ffma2(acc[1], w0.y, h0.y);
    ffma2(acc[2], w1.x, h1.x); ffma2(acc[3], w1.y, h1.y);
    ffma2(acc[4], w2.x, h2.x); ffma2(acc[5], w2.y, h2.y);
    ffma2(acc[6], w3.x, h3.x); ffma2(acc[7], w3.y, h3.y);
}
// 8 floats (2 ull2 each)
__device__ __forceinline__ void dot8(const ulonglong2* __restrict__ wp,
                                     const ulonglong2* __restrict__ hp, ull* acc) {
    ulonglong2 w0 = wp[0], w1 = wp[1];
    ulonglong2 h0 = hp[0], h1 = hp[1];
    ffma2(acc[0], w0.x, h0.x); ffma2(acc[1], w0.y, h0.y);
    ffma2(acc[2], w1.x, h1.x); ffma2(acc[3], w1.y, h1.y);
}
__device__ __forceinline__ float acc8_sum(const ull* acc) {
    float2 f0 = unpack2(acc[0]), f1 = unpack2(acc[1]), f2 = unpack2(acc[2]), f3 = unpack2(acc[3]);
    float2 f4 = unpack2(acc[4]), f5 = unpack2(acc[5]), f6 = unpack2(acc[6]), f7 = unpack2(acc[7]);
    float s0 = (f0.x + f0.y) + (f1.x + f1.y);
    float s1 = (f2.x + f2.y) + (f3.x + f3.y);
    float s2 = (f4.x + f4.y) + (f5.x + f5.y);
    float s3 = (f6.x + f6.y) + (f7.x + f7.y);
    return (s0 + s1) + (s2 + s3);
}

// ---------------- kernel 1: projection GEMM (fp32, f32x2) ----------------
__global__ void __launch_bounds__(256) gemm_pre(const float* __restrict__ x,
                                                const float* __restrict__ W_ru,
                                                const float* __restrict__ W_c,
                                                const float* __restrict__ b_ru,
                                                const float* __restrict__ b_c) {
    __shared__ float As[2][64 * 36];
    __shared__ float Bs[2][32 * 64];
    const int tid = threadIdx.x;
    const int n0 = blockIdx.x * 64;
    const int m0 = blockIdx.y * 64;

    const float* Wsrc = (n0 < 1024) ? (W_ru + (size_t)n0 * 1024 + 512)
                                    : (W_c + (size_t)(n0 - 1024) * 1024 + 512);

    const int arow = tid >> 3, ac = (tid & 7) * 4;
    const float* Ap0 = x + (size_t)(m0 + arow) * 512 + ac;
    const int bn = tid & 63, bk = (tid >> 6) * 4;
    const float* Bp0 = Wsrc + (size_t)bn * 1024 + bk;

    const int tx = tid & 15, ty = tid >> 4;

    ull acc[4][2];
#pragma unroll
    for (int i = 0; i < 4; i++) { acc[i][0] = 0ull; acc[i][1] = 0ull; }

    float4 ra0 = *(const float4*)(Ap0);
    float4 ra1 = *(const float4*)(Ap0 + 32 * 512);
    float4 rb0 = *(const float4*)(Bp0);
    float4 rb1 = *(const float4*)(Bp0 + 16);

    *(float4*)&As[0][arow * 36 + ac] = ra0;
    *(float4*)&As[0][(arow + 32) * 36 + ac] = ra1;
    Bs[0][(bk + 0) * 64 + bn] = rb0.x; Bs[0][(bk + 1) * 64 + bn] = rb0.y;
    Bs[0][(bk + 2) * 64 + bn] = rb0.z; Bs[0][(bk + 3) * 64 + bn] = rb0.w;
    Bs[0][(bk + 16) * 64 + bn] = rb1.x; Bs[0][(bk + 17) * 64 + bn] = rb1.y;
    Bs[0][(bk + 18) * 64 + bn] = rb1.z; Bs[0][(bk + 19) * 64 + bn] = rb1.w;
    __syncthreads();

    for (int kt = 0; kt < 16; kt++) {
        const int cur = kt & 1;
        if (kt < 15) {
            const float* ap = Ap0 + (kt + 1) * 32;
            ra0 = *(const float4*)(ap);
            ra1 = *(const float4*)(ap + 32 * 512);
            const float* bp = Bp0 + (kt + 1) * 32;
            rb0 = *(const float4*)(bp);
            rb1 = *(const float4*)(bp + 16);
        }
        const float* Arow = &As[cur][ty * 4 * 36];
        const float* Bbase = &Bs[cur][0];
#pragma unroll
        for (int kk = 0; kk < 32; kk++) {
            float av0 = Arow[kk], av1 = Arow[36 + kk], av2 = Arow[72 + kk], av3 = Arow[108 + kk];
            const ull* Bq = (const ull*)(Bbase + kk * 64);
            ull b0 = Bq[tx * 2], b1 = Bq[tx * 2 + 1];
            ull s0 = splat2(av0), s1 = splat2(av1), s2 = splat2(av2), s3 = splat2(av3);
            ffma2(acc[0][0], s0, b0); ffma2(acc[0][1], s0, b1);
            ffma2(acc[1][0], s1, b0); ffma2(acc[1][1], s1, b1);
            ffma2(acc[2][0], s2, b0); ffma2(acc[2][1], s2, b1);
            ffma2(acc[3][0], s3, b0); ffma2(acc[3][1], s3, b1);
        }
        if (kt < 15) {
            const int nb = (kt + 1) & 1;
            *(float4*)&As[nb][arow * 36 + ac] = ra0;
            *(float4*)&As[nb][(arow + 32) * 36 + ac] = ra1;
            Bs[nb][(bk + 0) * 64 + bn] = rb0.x; Bs[nb][(bk + 1) * 64 + bn] = rb0.y;
            Bs[nb][(bk + 2) * 64 + bn] = rb0.z; Bs[nb][(bk + 3) * 64 + bn] = rb0.w;
            Bs[nb][(bk + 16) * 64 + bn] = rb1.x; Bs[nb][(bk + 17) * 64 + bn] = rb1.y;
            Bs[nb][(bk + 18) * 64 + bn] = rb1.z; Bs[nb][(bk + 19) * 64 + bn] = rb1.w;
        }
        __syncthreads();
    }

    const float* bias = (n0 < 1024) ? (b_ru + n0) : (b_c + (n0 - 1024));
    const float4 bv = *(const float4*)&bias[tx * 4];
#pragma unroll
    for (int i = 0; i < 4; i++) {
        int m = m0 + ty * 4 + i;
        int bb = m >> 10, tt = m & 1023;
        float2 f0 = unpack2(acc[i][0]);
        float2 f1 = unpack2(acc[i][1]);
        float4 o = make_float4(f0.x + bv.x, f0.y + bv.y, f1.x + bv.z, f1.y + bv.w);
        *(float4*)&g_pre[((size_t)tt * 32 + bb) * 1536 + n0 + tx * 4] = o;
    }
}

// ---------------- group barrier: padded flags ----------------
__device__ __forceinline__ void bar_signal(int grp, int c, unsigned target) {
    asm volatile("st.release.gpu.u32 [%0], %1;"
                 :: "l"(g_flag + ((size_t)(grp * CPG + c) * 32)), "r"(target) : "memory");
}
__device__ __forceinline__ void bar_poll(int grp, unsigned target) {
    if (threadIdx.x < CPG) {
        const unsigned* fp = g_flag + ((size_t)(grp * CPG + threadIdx.x) * 32);
        unsigned v;
        do {
            asm volatile("ld.acquire.gpu.u32 %0, [%1];" : "=r"(v) : "l"(fp) : "memory");
        } while ((int)(v - target) < 0);
    }
    __syncthreads();
}

// ---------------- kernel 2: persistent recurrent scan (512 threads) ----------------
__global__ void __launch_bounds__(512, 1) scan_kernel(const float* __restrict__ W_ru,
                                                      const float* __restrict__ W_c,
                                                      const float* __restrict__ init_h,
                                                      float* __restrict__ out,
                                                      int has_last) {
    extern __shared__ float sm[];
    float* sWg = sm;                      // 64 x ROWP
    float* sWc = sWg + 64 * ROWP;         // 32 x ROWP
    float* sh  = sWc + 32 * ROWP;         // 4 x ROWP
    float* srh = sh + 4 * ROWP;           // 4 x ROWP
    __shared__ unsigned sBase;

    const int tid = threadIdx.x;
    const int grp = blockIdx.x >> 4;
    const int c   = blockIdx.x & 15;

    if (tid == 0) sBase = g_flag[(size_t)(grp * CPG + c) * 32];

    {
        const int gbase = c * 64;
        for (int i = tid; i < 64 * 128; i += 512) {
            int r = i >> 7, q = (i & 127) * 4;
            float4 v = *(const float4*)(W_ru + (size_t)(gbase + r) * 1024 + q);
            *(float4*)(sWg + r * ROWP + q) = v;
        }
        const int nbase = c * 32;
        for (int i = tid; i < 32 * 128; i += 512) {
            int r = i >> 7, q = (i & 127) * 4;
            float4 v = *(const float4*)(W_c + (size_t)(nbase + r) * 1024 + q);
            *(float4*)(sWc + r * ROWP + q) = v;
        }
    }
    {
        int b = tid >> 7, q = (tid & 127) * 4;
        float4 v = *(const float4*)(init_h + (size_t)(grp * 4 + b) * 512 + q);
        *(float4*)(sh + b * ROWP + q) = v;
    }
    __syncthreads();
    const unsigned base = sBase;

    // phase-1: pair of threads per (gate row, batch); h1 = INTERLEAVED 16-float blocks
    // bank groups: (gl*129 + h1*4) mod 8 = gl + 4*h1 -> all 8 distinct (conflict-free)
    const int pr = tid >> 1, h1 = tid & 1;
    const int gl = pr >> 2, bl = pr & 3;
    const int ggl = c * 64 + gl;
    const int gb  = grp * 4 + bl;
    const ulonglong2* wg_p = (const ulonglong2*)(sWg + gl * ROWP) + h1 * 4;
    const ulonglong2* sh_p = (const ulonglong2*)(sh + bl * ROWP) + h1 * 4;

    // phase-2: quad of threads per (cand row, batch); q4 = INTERLEAVED 8-float blocks
    // bank groups: (nl + 2*q4) mod 8 -> all 8 distinct
    const int q4 = tid & 3, d2 = tid >> 2;
    const int nl = d2 >> 2, bl2 = d2 & 3;
    const int n   = c * 32 + nl;
    const int gb2 = grp * 4 + bl2;
    const ulonglong2* wc_p = (const ulonglong2*)(sWc + nl * ROWP) + q4 * 2;

    const bool is_r = (ggl < 512);
    float* rz_dst = is_r ? (g_rh + (size_t)gb * 512 + ggl)
                         : (g_z + (size_t)gb * 512 + (ggl - 512));

    float xg = __ldg(&g_pre[(size_t)gb * 1536 + ggl]);

    for (int t = 0; t < Lv; t++) {
        // ---- phase 1: gates (16 interleaved 16-float blocks, stride 32 floats) ----
        float xc = __ldg(&g_pre[((size_t)t * 32 + gb2) * 1536 + 1024 + n]);  // prefetch
        ull a[8];
#pragma unroll
        for (int i = 0; i < 8; i++) a[i] = 0ull;
#pragma unroll
        for (int j = 0; j < 16; j++) dot16(wg_p + j * 8, sh_p + j * 8, a);
        float pre = acc8_sum(a);
        pre += __shfl_xor_sync(0xffffffffu, pre, 1);
        if (h1 == 0) {
            float gate = fast_sigmoid(pre + xg);
            float val = is_r ? (gate * sh[bl * ROWP + ggl]) : gate;
            __stcg(rz_dst, val);
        }

        __syncthreads();
        if (tid == 0) bar_signal(grp, c, base + 2u * t + 1u);
        bar_poll(grp, base + 2u * t + 1u);

        // ---- stage rh ----
        {
            int b = tid >> 7, q = (tid & 127) * 4;
            float4 v = __ldcg((const float4*)(g_rh + (size_t)(grp * 4 + b) * 512 + q));
            *(float4*)(srh + b * ROWP + q) = v;
        }
        float zv = __ldcg(&g_z[(size_t)gb2 * 512 + n]);
        __syncthreads();

        // ---- phase 2: candidate (16 interleaved 8-float blocks, stride 32 floats) ----
        const ulonglong2* srh_p = (const ulonglong2*)(srh + bl2 * ROWP) + q4 * 2;
        ull ca[8];
#pragma unroll
        for (int i = 0; i < 8; i++) ca[i] = 0ull;
#pragma unroll
        for (int j = 0; j < 16; j++) dot8(wc_p + j * 8, srh_p + j * 8, ca + (j & 1) * 4);
        float tot = acc8_sum(ca);
        tot += __shfl_xor_sync(0xffffffffu, tot, 1);
        tot += __shfl_xor_sync(0xffffffffu, tot, 2);

        if (t < Lv - 1) xg = __ldg(&g_pre[((size_t)(t + 1) * 32 + gb) * 1536 + ggl]);

        float hnew = 0.0f;
        if (q4 == 0) {
            float cand = fast_tanh(tot + xc);
            float hold = sh[bl2 * ROWP + n];
            hnew = hold + zv * (cand - hold);
            __stcg(&g_h[(size_t)gb2 * 512 + n], hnew);
        }

        __syncthreads();
        if (tid == 0) bar_signal(grp, c, base + 2u * t + 2u);

        // out-store off the critical path
        if (q4 == 0) {
            out[(size_t)gb2 * ((size_t)Lv * 512) + (size_t)t * 512 + n] = hnew;
            if (has_last && t == Lv - 1)
                out[(size_t)Bv * Lv * 512 + (size_t)gb2 * 512 + n] = hnew;
        }

        bar_poll(grp, base + 2u * t + 2u);

        // ---- restage h ----
        if (t < Lv - 1) {
            int b = tid >> 7, q = (tid & 127) * 4;
            float4 v = __ldcg((const float4*)(g_h + (size_t)(grp * 4 + b) * 512 + q));
            *(float4*)(sh + b * ROWP + q) = v;
            __syncthreads();
        }
    }
}

// ---------------- launch ----------------
extern "C" void kernel_launch(void* const* d_in, const int* in_sizes, int n_in,
                              void* d_out, int out_size) {
    const float* x      = (const float*)d_in[0];
    const float* init_h = (const float*)d_in[1];
    const float* W_ru   = (const float*)d_in[2];
    const float* b_ru   = (const float*)d_in[3];
    const float* W_c    = (const float*)d_in[4];
    const float* b_c    = (const float*)d_in[5];
    float* out = (float*)d_out;

    const int scan_smem = (64 * ROWP + 32 * ROWP + 8 * ROWP) * 4;  // 214,656 B
    cudaFuncSetAttribute(scan_kernel, cudaFuncAttributeMaxDynamicSharedMemorySize, scan_smem);

    int has_last = (out_size >= Bv * Lv * Hv + Bv * Hv) ? 1 : 0;

    gemm_pre<<<dim3(24, 512), 256>>>(x, W_ru, W_c, b_ru, b_c);
    scan_kernel<<<NGROUP * CPG, 512, scan_smem>>>(W_ru, W_c, init_h, out, has_last);
}

// round 10
// speedup vs baseline: 2.6462x; 1.3871x over previous
#include <cuda_runtime.h>
#include <cstdint>
#include <math.h>

typedef unsigned long long ull;

#define Bv 32
#define Lv 1024
#define Hv 512
#define NGROUP 8
#define CPG 16
#define WS 512   // smem row stride (floats); no padding needed for the strided-pair access

// ---------------- device scratch (no cudaMalloc allowed) ----------------
__device__ float g_pre[(size_t)Lv * Bv * 1536];   // [t][b][0..1023]=x_ru+b_ru, [1024..1535]=x_c+b_c
__device__ float g_h [Bv * Hv];
__device__ float g_rh[Bv * Hv];
__device__ float g_z [Bv * Hv];
__device__ unsigned int g_flag[NGROUP * CPG * 32];   // one flag per CTA, own 128B line

// ---------------- f32x2 helpers ----------------
__device__ __forceinline__ ull splat2(float x) {
    ull r; asm("mov.b64 %0, {%1, %1};" : "=l"(r) : "f"(x)); return r;
}
__device__ __forceinline__ float2 unpack2(ull v) {
    float2 f; asm("mov.b64 {%0, %1}, %2;" : "=f"(f.x), "=f"(f.y) : "l"(v)); return f;
}
__device__ __forceinline__ void ffma2(ull& d, ull a, ull b) {
    asm("fma.rn.f32x2 %0, %1, %2, %0;" : "+l"(d) : "l"(a), "l"(b));
}
__device__ __forceinline__ float fast_sigmoid(float x) {
    x = fminf(fmaxf(x, -30.0f), 30.0f);
    return 1.0f / (1.0f + __expf(-x));
}
__device__ __forceinline__ float fast_tanh(float x) {
    x = fminf(fmaxf(x, -15.0f), 15.0f);
    float e = __expf(2.0f * x);
    return (e - 1.0f) / (e + 1.0f);
}

// ---------------- kernel 1: projection GEMM (fp32, f32x2) ----------------
__global__ void __launch_bounds__(256) gemm_pre(const float* __restrict__ x,
                                                const float* __restrict__ W_ru,
                                                const float* __restrict__ W_c,
                                                const float* __restrict__ b_ru,
                                                const float* __restrict__ b_c) {
    __shared__ float As[2][64 * 36];
    __shared__ float Bs[2][32 * 64];
    const int tid = threadIdx.x;
    const int n0 = blockIdx.x * 64;
    const int m0 = blockIdx.y * 64;

    const float* Wsrc = (n0 < 1024) ? (W_ru + (size_t)n0 * 1024 + 512)
                                    : (W_c + (size_t)(n0 - 1024) * 1024 + 512);

    const int arow = tid >> 3, ac = (tid & 7) * 4;
    const float* Ap0 = x + (size_t)(m0 + arow) * 512 + ac;
    const int bn = tid & 63, bk = (tid >> 6) * 4;
    const float* Bp0 = Wsrc + (size_t)bn * 1024 + bk;

    const int tx = tid & 15, ty = tid >> 4;

    ull acc[4][2];
#pragma unroll
    for (int i = 0; i < 4; i++) { acc[i][0] = 0ull; acc[i][1] = 0ull; }

    float4 ra0 = *(const float4*)(Ap0);
    float4 ra1 = *(const float4*)(Ap0 + 32 * 512);
    float4 rb0 = *(const float4*)(Bp0);
    float4 rb1 = *(const float4*)(Bp0 + 16);

    *(float4*)&As[0][arow * 36 + ac] = ra0;
    *(float4*)&As[0][(arow + 32) * 36 + ac] = ra1;
    Bs[0][(bk + 0) * 64 + bn] = rb0.x; Bs[0][(bk + 1) * 64 + bn] = rb0.y;
    Bs[0][(bk + 2) * 64 + bn] = rb0.z; Bs[0][(bk + 3) * 64 + bn] = rb0.w;
    Bs[0][(bk + 16) * 64 + bn] = rb1.x; Bs[0][(bk + 17) * 64 + bn] = rb1.y;
    Bs[0][(bk + 18) * 64 + bn] = rb1.z; Bs[0][(bk + 19) * 64 + bn] = rb1.w;
    __syncthreads();

    for (int kt = 0; kt < 16; kt++) {
        const int cur = kt & 1;
        if (kt < 15) {
            const float* ap = Ap0 + (kt + 1) * 32;
            ra0 = *(const float4*)(ap);
            ra1 = *(const float4*)(ap + 32 * 512);
            const float* bp = Bp0 + (kt + 1) * 32;
            rb0 = *(const float4*)(bp);
            rb1 = *(const float4*)(bp + 16);
        }
        const float* Arow = &As[cur][ty * 4 * 36];
        const float* Bbase = &Bs[cur][0];
#pragma unroll
        for (int kk = 0; kk < 32; kk++) {
            float av0 = Arow[kk], av1 = Arow[36 + kk], av2 = Arow[72 + kk], av3 = Arow[108 + kk];
            const ull* Bq = (const ull*)(Bbase + kk * 64);
            ull b0 = Bq[tx * 2], b1 = Bq[tx * 2 + 1];
            ull s0 = splat2(av0), s1 = splat2(av1), s2 = splat2(av2), s3 = splat2(av3);
            ffma2(acc[0][0], s0, b0); ffma2(acc[0][1], s0, b1);
            ffma2(acc[1][0], s1, b0); ffma2(acc[1][1], s1, b1);
            ffma2(acc[2][0], s2, b0); ffma2(acc[2][1], s2, b1);
            ffma2(acc[3][0], s3, b0); ffma2(acc[3][1], s3, b1);
        }
        if (kt < 15) {
            const int nb = (kt + 1) & 1;
            *(float4*)&As[nb][arow * 36 + ac] = ra0;
            *(float4*)&As[nb][(arow + 32) * 36 + ac] = ra1;
            Bs[nb][(bk + 0) * 64 + bn] = rb0.x; Bs[nb][(bk + 1) * 64 + bn] = rb0.y;
            Bs[nb][(bk + 2) * 64 + bn] = rb0.z; Bs[nb][(bk + 3) * 64 + bn] = rb0.w;
            Bs[nb][(bk + 16) * 64 + bn] = rb1.x; Bs[nb][(bk + 17) * 64 + bn] = rb1.y;
            Bs[nb][(bk + 18) * 64 + bn] = rb1.z; Bs[nb][(bk + 19) * 64 + bn] = rb1.w;
        }
        __syncthreads();
    }

    const float* bias = (n0 < 1024) ? (b_ru + n0) : (b_c + (n0 - 1024));
    const float4 bv = *(const float4*)&bias[tx * 4];
#pragma unroll
    for (int i = 0; i < 4; i++) {
        int m = m0 + ty * 4 + i;
        int bb = m >> 10, tt = m & 1023;
        float2 f0 = unpack2(acc[i][0]);
        float2 f1 = unpack2(acc[i][1]);
        float4 o = make_float4(f0.x + bv.x, f0.y + bv.y, f1.x + bv.z, f1.y + bv.w);
        *(float4*)&g_pre[((size_t)tt * 32 + bb) * 1536 + n0 + tx * 4] = o;
    }
}

// ---------------- group barrier: padded flags ----------------
__device__ __forceinline__ void bar_signal(int grp, int c, unsigned target) {
    asm volatile("st.release.gpu.u32 [%0], %1;"
                 :: "l"(g_flag + ((size_t)(grp * CPG + c) * 32)), "r"(target) : "memory");
}
__device__ __forceinline__ void bar_poll(int grp, unsigned target) {
    if (threadIdx.x < CPG) {
        const unsigned* fp = g_flag + ((size_t)(grp * CPG + threadIdx.x) * 32);
        unsigned v;
        do {
            asm volatile("ld.acquire.gpu.u32 %0, [%1];" : "=r"(v) : "l"(fp) : "memory");
        } while ((int)(v - target) < 0);
    }
    __syncthreads();
}

// ---------------- kernel 2: persistent recurrent scan (512 threads) ----------------
// Warp = register tile: phase-1 4 rows x 4 batches, phase-2 2 rows x 4 batches.
// Lane l covers k-pairs {2l + 64*i}. Value-splitting butterfly reduction.
__global__ void __launch_bounds__(512, 1) scan_kernel(const float* __restrict__ W_ru,
                                                      const float* __restrict__ W_c,
                                                      const float* __restrict__ init_h,
                                                      float* __restrict__ out,
                                                      int has_last) {
    extern __shared__ float sm[];
    float* sWg = sm;                      // 64 x WS
    float* sWc = sWg + 64 * WS;           // 32 x WS
    float* sh  = sWc + 32 * WS;           // 4 x WS
    float* srh = sh + 4 * WS;             // 4 x WS
    __shared__ unsigned sBase;

    const int tid = threadIdx.x;
    const int w = tid >> 5, l = tid & 31;
    const int grp = blockIdx.x >> 4;
    const int c   = blockIdx.x & 15;

    if (tid == 0) sBase = g_flag[(size_t)(grp * CPG + c) * 32];

    {
        const int gbase = c * 64;
        for (int i = tid; i < 64 * 128; i += 512) {
            int r = i >> 7, q = (i & 127) * 4;
            *(float4*)(sWg + r * WS + q) = *(const float4*)(W_ru + (size_t)(gbase + r) * 1024 + q);
        }
        const int nbase = c * 32;
        for (int i = tid; i < 32 * 128; i += 512) {
            int r = i >> 7, q = (i & 127) * 4;
            *(float4*)(sWc + r * WS + q) = *(const float4*)(W_c + (size_t)(nbase + r) * 1024 + q);
        }
    }
    {
        int b = tid >> 7, q = (tid & 127) * 4;
        *(float4*)(sh + b * WS + q) = *(const float4*)(init_h + (size_t)(grp * 4 + b) * 512 + q);
    }
    __syncthreads();
    const unsigned base = sBase;

    // phase-1 output mapping: value idx = (l>>1)&15 = row*4 + batch (rows within warp's 4)
    const int oidx  = (l >> 1) & 15;
    const int orow  = oidx >> 2, obat = oidx & 3;
    const int ggl   = c * 64 + w * 4 + orow;     // global gate row 0..1023
    const int gbo   = grp * 4 + obat;
    const bool is_r = (ggl < 512);
    float* rz_dst = is_r ? (g_rh + (size_t)gbo * 512 + ggl)
                         : (g_z + (size_t)gbo * 512 + (ggl - 512));
    const bool p1out = ((l & 1) == 0);

    // phase-2 output mapping: value idx = (l>>2)&7 = row*4 + batch (rows within warp's 2)
    const int oidx2 = (l >> 2) & 7;
    const int orow2 = oidx2 >> 2, obat2 = oidx2 & 3;
    const int n_o   = c * 32 + w * 2 + orow2;
    const int gb2o  = grp * 4 + obat2;
    const bool p2out = ((l & 3) == 0);

    const float* wg = sWg + (w * 4) * WS + 2 * l;
    const float* wc = sWc + (w * 2) * WS + 2 * l;
    const float* hh = sh + 2 * l;
    const float* rr = srh + 2 * l;

    float xg = __ldg(&g_pre[(size_t)gbo * 1536 + ggl]);

    for (int t = 0; t < Lv; t++) {
        float xc = __ldg(&g_pre[((size_t)t * 32 + gb2o) * 1536 + 1024 + n_o]);  // prefetch

        // ---- phase 1: 4 rows x 4 batches per warp ----
        ull a[16];
#pragma unroll
        for (int i = 0; i < 16; i++) a[i] = 0ull;
#pragma unroll
        for (int i = 0; i < 8; i++) {
            const int off = 64 * i;
            ull w0 = *(const ull*)(wg + off);
            ull w1 = *(const ull*)(wg + WS + off);
            ull w2 = *(const ull*)(wg + 2 * WS + off);
            ull w3 = *(const ull*)(wg + 3 * WS + off);
            ull h0 = *(const ull*)(hh + off);
            ull h1 = *(const ull*)(hh + WS + off);
            ull h2 = *(const ull*)(hh + 2 * WS + off);
            ull h3 = *(const ull*)(hh + 3 * WS + off);
            ffma2(a[0],  w0, h0); ffma2(a[1],  w0, h1); ffma2(a[2],  w0, h2); ffma2(a[3],  w0, h3);
            ffma2(a[4],  w1, h0); ffma2(a[5],  w1, h1); ffma2(a[6],  w1, h2); ffma2(a[7],  w1, h3);
            ffma2(a[8],  w2, h0); ffma2(a[9],  w2, h1); ffma2(a[10], w2, h2); ffma2(a[11], w2, h3);
            ffma2(a[12], w3, h0); ffma2(a[13], w3, h1); ffma2(a[14], w3, h2); ffma2(a[15], w3, h3);
        }
        float vals[16];
#pragma unroll
        for (int v = 0; v < 16; v++) { float2 f = unpack2(a[v]); vals[v] = f.x + f.y; }
        // value-splitting butterfly: idx bit3..0 <- lane bit4..1
#pragma unroll
        for (int i = 0; i < 8; i++) {
            float send = (l & 16) ? vals[i] : vals[i + 8];
            float recv = __shfl_xor_sync(0xffffffffu, send, 16);
            vals[i] = ((l & 16) ? vals[i + 8] : vals[i]) + recv;
        }
#pragma unroll
        for (int i = 0; i < 4; i++) {
            float send = (l & 8) ? vals[i] : vals[i + 4];
            float recv = __shfl_xor_sync(0xffffffffu, send, 8);
            vals[i] = ((l & 8) ? vals[i + 4] : vals[i]) + recv;
        }
#pragma unroll
        for (int i = 0; i < 2; i++) {
            float send = (l & 4) ? vals[i] : vals[i + 2];
            float recv = __shfl_xor_sync(0xffffffffu, send, 4);
            vals[i] = ((l & 4) ? vals[i + 2] : vals[i]) + recv;
        }
        {
            float send = (l & 2) ? vals[0] : vals[1];
            float recv = __shfl_xor_sync(0xffffffffu, send, 2);
            vals[0] = ((l & 2) ? vals[1] : vals[0]) + recv;
        }
        float tot1 = vals[0] + __shfl_xor_sync(0xffffffffu, vals[0], 1);

        if (p1out) {
            float gate = fast_sigmoid(tot1 + xg);
            float val = is_r ? (gate * sh[obat * WS + ggl]) : gate;
            __stcg(rz_dst, val);
        }

        __syncthreads();
        if (tid == 0) bar_signal(grp, c, base + 2u * t + 1u);
        bar_poll(grp, base + 2u * t + 1u);

        // ---- stage rh ----
        {
            int b = tid >> 7, q = (tid & 127) * 4;
            float4 v = __ldcg((const float4*)(g_rh + (size_t)(grp * 4 + b) * 512 + q));
            *(float4*)(srh + b * WS + q) = v;
        }
        float zv = p2out ? __ldcg(&g_z[(size_t)gb2o * 512 + n_o]) : 0.0f;
        __syncthreads();

        // ---- phase 2: 2 rows x 4 batches per warp ----
        ull ca[8];
#pragma unroll
        for (int i = 0; i < 8; i++) ca[i] = 0ull;
#pragma unroll
        for (int i = 0; i < 8; i++) {
            const int off = 64 * i;
            ull w0 = *(const ull*)(wc + off);
            ull w1 = *(const ull*)(wc + WS + off);
            ull h0 = *(const ull*)(rr + off);
            ull h1 = *(const ull*)(rr + WS + off);
            ull h2 = *(const ull*)(rr + 2 * WS + off);
            ull h3 = *(const ull*)(rr + 3 * WS + off);
            ffma2(ca[0], w0, h0); ffma2(ca[1], w0, h1); ffma2(ca[2], w0, h2); ffma2(ca[3], w0, h3);
            ffma2(ca[4], w1, h0); ffma2(ca[5], w1, h1); ffma2(ca[6], w1, h2); ffma2(ca[7], w1, h3);
        }
        float v2[8];
#pragma unroll
        for (int v = 0; v < 8; v++) { float2 f = unpack2(ca[v]); v2[v] = f.x + f.y; }
        // idx bit2..0 <- lane bit4..2
#pragma unroll
        for (int i = 0; i < 4; i++) {
            float send = (l & 16) ? v2[i] : v2[i + 4];
            float recv = __shfl_xor_sync(0xffffffffu, send, 16);
            v2[i] = ((l & 16) ? v2[i + 4] : v2[i]) + recv;
        }
#pragma unroll
        for (int i = 0; i < 2; i++) {
            float send = (l & 8) ? v2[i] : v2[i + 2];
            float recv = __shfl_xor_sync(0xffffffffu, send, 8);
            v2[i] = ((l & 8) ? v2[i + 2] : v2[i]) + recv;
        }
        {
            float send = (l & 4) ? v2[0] : v2[1];
            float recv = __shfl_xor_sync(0xffffffffu, send, 4);
            v2[0] = ((l & 4) ? v2[1] : v2[0]) + recv;
        }
        float tot2 = v2[0];
        tot2 += __shfl_xor_sync(0xffffffffu, tot2, 2);
        tot2 += __shfl_xor_sync(0xffffffffu, tot2, 1);

        if (t < Lv - 1) xg = __ldg(&g_pre[((size_t)(t + 1) * 32 + gbo) * 1536 + ggl]);

        float hnew = 0.0f;
        if (p2out) {
            float cand = fast_tanh(tot2 + xc);
            float hold = sh[obat2 * WS + n_o];
            hnew = hold + zv * (cand - hold);
            __stcg(&g_h[(size_t)gb2o * 512 + n_o], hnew);
        }

        __syncthreads();
        if (tid == 0) bar_signal(grp, c, base + 2u * t + 2u);

        // out-store off the critical path
        if (p2out) {
            out[(size_t)gb2o * ((size_t)Lv * 512) + (size_t)t * 512 + n_o] = hnew;
            if (has_last && t == Lv - 1)
                out[(size_t)Bv * Lv * 512 + (size_t)gb2o * 512 + n_o] = hnew;
        }

        bar_poll(grp, base + 2u * t + 2u);

        // ---- restage h ----
        if (t < Lv - 1) {
            int b = tid >> 7, q = (tid & 127) * 4;
            float4 v = __ldcg((const float4*)(g_h + (size_t)(grp * 4 + b) * 512 + q));
            *(float4*)(sh + b * WS + q) = v;
            __syncthreads();
        }
    }
}

// ---------------- launch ----------------
extern "C" void kernel_launch(void* const* d_in, const int* in_sizes, int n_in,
                              void* d_out, int out_size) {
    const float* x      = (const float*)d_in[0];
    const float* init_h = (const float*)d_in[1];
    const float* W_ru   = (const float*)d_in[2];
    const float* b_ru   = (const float*)d_in[3];
    const float* W_c    = (const float*)d_in[4];
    const float* b_c    = (const float*)d_in[5];
    float* out = (float*)d_out;

    const int scan_smem = (64 * WS + 32 * WS + 8 * WS) * 4;  // 212,992 B
    cudaFuncSetAttribute(scan_kernel, cudaFuncAttributeMaxDynamicSharedMemorySize, scan_smem);

    int has_last = (out_size >= Bv * Lv * Hv + Bv * Hv) ? 1 : 0;

    gemm_pre<<<dim3(24, 512), 256>>>(x, W_ru, W_c, b_ru, b_c);
    scan_kernel<<<NGROUP * CPG, 512, scan_smem>>>(W_ru, W_c, init_h, out, has_last);
}

// round 11
// speedup vs baseline: 3.0513x; 1.1531x over previous
#include <cuda_runtime.h>
#include <cstdint>
#include <math.h>

typedef unsigned long long ull;

#define Bv 32
#define Lv 1024
#define Hv 512
#define NGROUP 8
#define CPG 16
#define WS 512

// ---------------- device scratch (no cudaMalloc allowed) ----------------
__device__ float g_pre[(size_t)Lv * Bv * 1536];   // [t][b][0..511]=r-pre, [512..1023]=z-pre, [1024..1535]=c-pre
__device__ float g_h [Bv * Hv];
__device__ float g_rh[Bv * Hv];
__device__ unsigned int g_flag[NGROUP * CPG * 32];   // one flag per CTA, own 128B line

// ---------------- f32x2 helpers ----------------
__device__ __forceinline__ ull splat2(float x) {
    ull r; asm("mov.b64 %0, {%1, %1};" : "=l"(r) : "f"(x)); return r;
}
__device__ __forceinline__ float2 unpack2(ull v) {
    float2 f; asm("mov.b64 {%0, %1}, %2;" : "=f"(f.x), "=f"(f.y) : "l"(v)); return f;
}
__device__ __forceinline__ void ffma2(ull& d, ull a, ull b) {
    asm("fma.rn.f32x2 %0, %1, %2, %0;" : "+l"(d) : "l"(a), "l"(b));
}
__device__ __forceinline__ float fast_sigmoid(float x) {
    x = fminf(fmaxf(x, -30.0f), 30.0f);
    return 1.0f / (1.0f + __expf(-x));
}
__device__ __forceinline__ float fast_tanh(float x) {
    x = fminf(fmaxf(x, -15.0f), 15.0f);
    float e = __expf(2.0f * x);
    return (e - 1.0f) / (e + 1.0f);
}

// ---------------- kernel 1: projection GEMM (fp32, f32x2) ----------------
__global__ void __launch_bounds__(256) gemm_pre(const float* __restrict__ x,
                                                const float* __restrict__ W_ru,
                                                const float* __restrict__ W_c,
                                                const float* __restrict__ b_ru,
                                                const float* __restrict__ b_c) {
    __shared__ float As[2][64 * 36];
    __shared__ float Bs[2][32 * 64];
    const int tid = threadIdx.x;
    const int n0 = blockIdx.x * 64;
    const int m0 = blockIdx.y * 64;

    const float* Wsrc = (n0 < 1024) ? (W_ru + (size_t)n0 * 1024 + 512)
                                    : (W_c + (size_t)(n0 - 1024) * 1024 + 512);

    const int arow = tid >> 3, ac = (tid & 7) * 4;
    const float* Ap0 = x + (size_t)(m0 + arow) * 512 + ac;
    const int bn = tid & 63, bk = (tid >> 6) * 4;
    const float* Bp0 = Wsrc + (size_t)bn * 1024 + bk;

    const int tx = tid & 15, ty = tid >> 4;

    ull acc[4][2];
#pragma unroll
    for (int i = 0; i < 4; i++) { acc[i][0] = 0ull; acc[i][1] = 0ull; }

    float4 ra0 = *(const float4*)(Ap0);
    float4 ra1 = *(const float4*)(Ap0 + 32 * 512);
    float4 rb0 = *(const float4*)(Bp0);
    float4 rb1 = *(const float4*)(Bp0 + 16);

    *(float4*)&As[0][arow * 36 + ac] = ra0;
    *(float4*)&As[0][(arow + 32) * 36 + ac] = ra1;
    Bs[0][(bk + 0) * 64 + bn] = rb0.x; Bs[0][(bk + 1) * 64 + bn] = rb0.y;
    Bs[0][(bk + 2) * 64 + bn] = rb0.z; Bs[0][(bk + 3) * 64 + bn] = rb0.w;
    Bs[0][(bk + 16) * 64 + bn] = rb1.x; Bs[0][(bk + 17) * 64 + bn] = rb1.y;
    Bs[0][(bk + 18) * 64 + bn] = rb1.z; Bs[0][(bk + 19) * 64 + bn] = rb1.w;
    __syncthreads();

    for (int kt = 0; kt < 16; kt++) {
        const int cur = kt & 1;
        if (kt < 15) {
            const float* ap = Ap0 + (kt + 1) * 32;
            ra0 = *(const float4*)(ap);
            ra1 = *(const float4*)(ap + 32 * 512);
            const float* bp = Bp0 + (kt + 1) * 32;
            rb0 = *(const float4*)(bp);
            rb1 = *(const float4*)(bp + 16);
        }
        const float* Arow = &As[cur][ty * 4 * 36];
        const float* Bbase = &Bs[cur][0];
#pragma unroll
        for (int kk = 0; kk < 32; kk++) {
            float av0 = Arow[kk], av1 = Arow[36 + kk], av2 = Arow[72 + kk], av3 = Arow[108 + kk];
            const ull* Bq = (const ull*)(Bbase + kk * 64);
            ull b0 = Bq[tx * 2], b1 = Bq[tx * 2 + 1];
            ull s0 = splat2(av0), s1 = splat2(av1), s2 = splat2(av2), s3 = splat2(av3);
            ffma2(acc[0][0], s0, b0); ffma2(acc[0][1], s0, b1);
            ffma2(acc[1][0], s1, b0); ffma2(acc[1][1], s1, b1);
            ffma2(acc[2][0], s2, b0); ffma2(acc[2][1], s2, b1);
            ffma2(acc[3][0], s3, b0); ffma2(acc[3][1], s3, b1);
        }
        if (kt < 15) {
            const int nb = (kt + 1) & 1;
            *(float4*)&As[nb][arow * 36 + ac] = ra0;
            *(float4*)&As[nb][(arow + 32) * 36 + ac] = ra1;
            Bs[nb][(bk + 0) * 64 + bn] = rb0.x; Bs[nb][(bk + 1) * 64 + bn] = rb0.y;
            Bs[nb][(bk + 2) * 64 + bn] = rb0.z; Bs[nb][(bk + 3) * 64 + bn] = rb0.w;
            Bs[nb][(bk + 16) * 64 + bn] = rb1.x; Bs[nb][(bk + 17) * 64 + bn] = rb1.y;
            Bs[nb][(bk + 18) * 64 + bn] = rb1.z; Bs[nb][(bk + 19) * 64 + bn] = rb1.w;
        }
        __syncthreads();
    }

    const float* bias = (n0 < 1024) ? (b_ru + n0) : (b_c + (n0 - 1024));
    const float4 bv = *(const float4*)&bias[tx * 4];
#pragma unroll
    for (int i = 0; i < 4; i++) {
        int m = m0 + ty * 4 + i;
        int bb = m >> 10, tt = m & 1023;
        float2 f0 = unpack2(acc[i][0]);
        float2 f1 = unpack2(acc[i][1]);
        float4 o = make_float4(f0.x + bv.x, f0.y + bv.y, f1.x + bv.z, f1.y + bv.w);
        *(float4*)&g_pre[((size_t)tt * 32 + bb) * 1536 + n0 + tx * 4] = o;
    }
}

// ---------------- group barrier ----------------
__device__ __forceinline__ void bar_signal(int grp, int c, unsigned target) {
    asm volatile("st.release.gpu.u32 [%0], %1;"
                 :: "l"(g_flag + ((size_t)(grp * CPG + c) * 32)), "r"(target) : "memory");
}
__device__ __forceinline__ void bar_poll(int grp, unsigned target) {
    if (threadIdx.x < CPG) {
        const unsigned* fp = g_flag + ((size_t)(grp * CPG + threadIdx.x) * 32);
        unsigned v;
        do {
            asm volatile("ld.acquire.gpu.u32 %0, [%1];" : "=r"(v) : "l"(fp) : "memory");
        } while ((int)(v - target) < 0);
    }
    __syncthreads();
}

// ---------------- scan microkernel pieces ----------------
// warp tile: 4 rows x 4 batches over a 256-wide k-half; lane covers k-pairs {2l + 64i}
__device__ __forceinline__ void mk44(const float* __restrict__ wb,
                                     const float* __restrict__ hb, ull* a) {
#pragma unroll
    for (int i = 0; i < 4; i++) {
        const int off = 64 * i;
        ull w0 = *(const ull*)(wb + off);
        ull w1 = *(const ull*)(wb + WS + off);
        ull w2 = *(const ull*)(wb + 2 * WS + off);
        ull w3 = *(const ull*)(wb + 3 * WS + off);
        ull h0 = *(const ull*)(hb + off);
        ull h1 = *(const ull*)(hb + WS + off);
        ull h2 = *(const ull*)(hb + 2 * WS + off);
        ull h3 = *(const ull*)(hb + 3 * WS + off);
        ffma2(a[0],  w0, h0); ffma2(a[1],  w0, h1); ffma2(a[2],  w0, h2); ffma2(a[3],  w0, h3);
        ffma2(a[4],  w1, h0); ffma2(a[5],  w1, h1); ffma2(a[6],  w1, h2); ffma2(a[7],  w1, h3);
        ffma2(a[8],  w2, h0); ffma2(a[9],  w2, h1); ffma2(a[10], w2, h2); ffma2(a[11], w2, h3);
        ffma2(a[12], w3, h0); ffma2(a[13], w3, h1); ffma2(a[14], w3, h2); ffma2(a[15], w3, h3);
    }
}
// value-splitting butterfly: 16 values over 32 lanes -> every lane holds value (l>>1)&15
__device__ __forceinline__ float reduce16(const ull* a, int l) {
    float vals[16];
#pragma unroll
    for (int v = 0; v < 16; v++) { float2 f = unpack2(a[v]); vals[v] = f.x + f.y; }
#pragma unroll
    for (int i = 0; i < 8; i++) {
        float send = (l & 16) ? vals[i] : vals[i + 8];
        float recv = __shfl_xor_sync(0xffffffffu, send, 16);
        vals[i] = ((l & 16) ? vals[i + 8] : vals[i]) + recv;
    }
#pragma unroll
    for (int i = 0; i < 4; i++) {
        float send = (l & 8) ? vals[i] : vals[i + 4];
        float recv = __shfl_xor_sync(0xffffffffu, send, 8);
        vals[i] = ((l & 8) ? vals[i + 4] : vals[i]) + recv;
    }
#pragma unroll
    for (int i = 0; i < 2; i++) {
        float send = (l & 4) ? vals[i] : vals[i + 2];
        float recv = __shfl_xor_sync(0xffffffffu, send, 4);
        vals[i] = ((l & 4) ? vals[i + 2] : vals[i]) + recv;
    }
    {
        float send = (l & 2) ? vals[0] : vals[1];
        float recv = __shfl_xor_sync(0xffffffffu, send, 2);
        vals[0] = ((l & 2) ? vals[1] : vals[0]) + recv;
    }
    return vals[0] + __shfl_xor_sync(0xffffffffu, vals[0], 1);
}

// ---------------- kernel 2: persistent scan, r/z/cand split ----------------
// CTA c of group: r rows [c*32,+32), z rows [512+c*32,+32), cand rows [c*32,+32), 4 batches.
// 16 warps = 8 row-groups (4 rows) x 2 k-halves; cross-warp combine via smem.
__global__ void __launch_bounds__(512, 1) scan_kernel(const float* __restrict__ W_ru,
                                                      const float* __restrict__ W_c,
                                                      const float* __restrict__ init_h,
                                                      float* __restrict__ out,
                                                      int has_last) {
    extern __shared__ float sm[];
    float* sWr = sm;                       // 32 x 512
    float* sWz = sWr + 32 * WS;            // 32 x 512
    float* sWc = sWz + 32 * WS;            // 32 x 512
    float* sh  = sWc + 32 * WS;            // 4 x 512
    float* srh = sh + 4 * WS;              // 4 x 512
    float* redR = srh + 4 * WS;            // 8 x 16
    float* redZ = redR + 128;              // 8 x 16
    float* redC = redZ + 128;              // 8 x 16
    __shared__ unsigned sBase;

    const int tid = threadIdx.x;
    const int w = tid >> 5, l = tid & 31;
    const int rg = w >> 1, kh = w & 1;
    const int grp = blockIdx.x >> 4;
    const int c   = blockIdx.x & 15;

    if (tid == 0) sBase = g_flag[(size_t)(grp * CPG + c) * 32];

    // --- weights: 32 rows each of Wr (ru rows c*32+), Wz (ru rows 512+c*32+), Wc ---
    for (int i = tid; i < 32 * 128; i += 512) {
        int r = i >> 7, q = (i & 127) * 4;
        *(float4*)(sWr + r * WS + q) = *(const float4*)(W_ru + (size_t)(c * 32 + r) * 1024 + q);
        *(float4*)(sWz + r * WS + q) = *(const float4*)(W_ru + (size_t)(512 + c * 32 + r) * 1024 + q);
        *(float4*)(sWc + r * WS + q) = *(const float4*)(W_c + (size_t)(c * 32 + r) * 1024 + q);
    }
    {
        int b = tid >> 7, q = (tid & 127) * 4;
        *(float4*)(sh + b * WS + q) = *(const float4*)(init_h + (size_t)(grp * 4 + b) * 512 + q);
    }
    __syncthreads();
    const unsigned base = sBase;

    // finalizer mapping (kh==0, even lanes): one (row_local, batch) each
    const int oidx = (l >> 1) & 15;
    const int row_local = rg * 4 + (oidx >> 2);
    const int bat = oidx & 3;
    const int nn  = c * 32 + row_local;        // global row index (same for r / z / cand)
    const int gbo = grp * 4 + bat;             // global batch
    const bool fin = (kh == 0) && ((l & 1) == 0);
    const int ridx = rg * 16 + oidx;

    // microkernel bases
    const float* wr = sWr + (rg * 4) * WS + kh * 256 + 2 * l;
    const float* wz = sWz + (rg * 4) * WS + kh * 256 + 2 * l;
    const float* wc = sWc + (rg * 4) * WS + kh * 256 + 2 * l;
    const float* hh = sh + kh * 256 + 2 * l;
    const float* rr = srh + kh * 256 + 2 * l;

    float xr = 0.f, xz = 0.f, xc = 0.f;
    if (fin) {
        const float* p = g_pre + (size_t)gbo * 1536;
        xr = __ldg(p + nn); xz = __ldg(p + 512 + nn); xc = __ldg(p + 1024 + nn);
    }

    for (int t = 0; t < Lv; t++) {
        // ---- phase R: reset gates ----
        ull a[16];
#pragma unroll
        for (int i = 0; i < 16; i++) a[i] = 0ull;
        mk44(wr, hh, a);
        float totR = reduce16(a, l);
        if (kh == 1 && (l & 1) == 0) redR[ridx] = totR;
        __syncthreads();
        if (fin) {
            float gate = fast_sigmoid(totR + redR[ridx] + xr);
            __stcg(&g_rh[(size_t)gbo * 512 + nn], gate * sh[bat * WS + nn]);
        }
        __syncthreads();
        if (tid == 0) bar_signal(grp, c, base + 2u * t + 1u);

        // ---- phase Z: update gates (local; hides barrier-1) ----
#pragma unroll
        for (int i = 0; i < 16; i++) a[i] = 0ull;
        mk44(wz, hh, a);
        float totZ = reduce16(a, l);
        if (kh == 1 && (l & 1) == 0) redZ[ridx] = totZ;

        bar_poll(grp, base + 2u * t + 1u);   // includes __syncthreads (covers redZ)

        // ---- stage rh ----
        {
            int b = tid >> 7, q = (tid & 127) * 4;
            float4 v = __ldcg((const float4*)(g_rh + (size_t)(grp * 4 + b) * 512 + q));
            *(float4*)(srh + b * WS + q) = v;
        }
        float zv = 0.f;
        if (fin) zv = fast_sigmoid(totZ + redZ[ridx] + xz);
        __syncthreads();

        // ---- phase C: candidate + blend ----
#pragma unroll
        for (int i = 0; i < 16; i++) a[i] = 0ull;
        mk44(wc, rr, a);
        float totC = reduce16(a, l);
        if (kh == 1 && (l & 1) == 0) redC[ridx] = totC;
        __syncthreads();
        float hnew = 0.f;
        if (fin) {
            float cand = fast_tanh(totC + redC[ridx] + xc);
            float hold = sh[bat * WS + nn];
            hnew = hold + zv * (cand - hold);
            __stcg(&g_h[(size_t)gbo * 512 + nn], hnew);
        }
        __syncthreads();
        if (tid == 0) bar_signal(grp, c, base + 2u * t + 2u);

        // off-critical-path: out store + next-step prefetch (overlap poll-2)
        if (fin) {
            out[(size_t)gbo * ((size_t)Lv * 512) + (size_t)t * 512 + nn] = hnew;
            if (has_last && t == Lv - 1)
                out[(size_t)Bv * Lv * 512 + (size_t)gbo * 512 + nn] = hnew;
            if (t < Lv - 1) {
                const float* p = g_pre + ((size_t)(t + 1) * 32 + gbo) * 1536;
                xr = __ldg(p + nn); xz = __ldg(p + 512 + nn); xc = __ldg(p + 1024 + nn);
            }
        }

        bar_poll(grp, base + 2u * t + 2u);

        // ---- restage h ----
        if (t < Lv - 1) {
            int b = tid >> 7, q = (tid & 127) * 4;
            float4 v = __ldcg((const float4*)(g_h + (size_t)(grp * 4 + b) * 512 + q));
            *(float4*)(sh + b * WS + q) = v;
            __syncthreads();
        }
    }
}

// ---------------- launch ----------------
extern "C" void kernel_launch(void* const* d_in, const int* in_sizes, int n_in,
                              void* d_out, int out_size) {
    const float* x      = (const float*)d_in[0];
    const float* init_h = (const float*)d_in[1];
    const float* W_ru   = (const float*)d_in[2];
    const float* b_ru   = (const float*)d_in[3];
    const float* W_c    = (const float*)d_in[4];
    const float* b_c    = (const float*)d_in[5];
    float* out = (float*)d_out;

    const int scan_smem = (3 * 32 * WS + 8 * WS + 3 * 128) * 4;  // 214,528 B
    cudaFuncSetAttribute(scan_kernel, cudaFuncAttributeMaxDynamicSharedMemorySize, scan_smem);

    int has_last = (out_size >= Bv * Lv * Hv + Bv * Hv) ? 1 : 0;

    gemm_pre<<<dim3(24, 512), 256>>>(x, W_ru, W_c, b_ru, b_c);
    scan_kernel<<<NGROUP * CPG, 512, scan_smem>>>(W_ru, W_c, init_h, out, has_last);
}